// round 7
// baseline (speedup 1.0000x reference)
#include <cuda_runtime.h>

#define NC 22
#define NP 1024
#define BMAX 256
#define CHUNKS 8          // kernel B: blocks per batch
#define TPB_B 64          // kernel B threads (each handles 2 p's): CHUNKS*TPB_B*2 == NP
#define TPB_A 128
#define MARGIN 0.01f

typedef unsigned long long ull;

__device__ ulonglong2 g_A[BMAX][NP / 2];   // ((-2gx_e,-2gx_o),(-2gy_e,-2gy_o))
__device__ ulonglong2 g_Bt[BMAX][NP / 2];  // ((-2gz_e,-2gz_o),(|g_e|^2,|g_o|^2))
__device__ float4     g_xp[BMAX][NP];      // (ax, ay, az, |a|^2)
__device__ int        g_is_sym[BMAX];
__device__ float      g_partial[BMAX];           // asym/diag per-batch partials
__device__ float      g_chunk[BMAX * CHUNKS];    // sym per-block partials
__device__ unsigned   g_done;                    // self-resetting via atomicInc wrap

__device__ __forceinline__ ull fma2(ull a, ull b, ull c) {
    ull d;
    asm("fma.rn.f32x2 %0, %1, %2, %3;" : "=l"(d) : "l"(a), "l"(b), "l"(c));
    return d;
}
__device__ __forceinline__ ull pack2(float lo, float hi) {
    ull d;
    asm("mov.b64 %0, {%1, %2};" : "=l"(d) : "f"(lo), "f"(hi));
    return d;
}
__device__ __forceinline__ void unpack2(ull v, float& lo, float& hi) {
    asm("mov.b64 {%0, %1}, %2;" : "=f"(lo), "=f"(hi) : "l"(v));
}

__device__ __forceinline__ void quat2rot(float w, float x, float y, float z, float* R) {
    R[0] = 1.f - 2.f * (y * y + z * z);
    R[1] = 2.f * (x * y - z * w);
    R[2] = 2.f * (x * z + y * w);
    R[3] = 2.f * (x * y + z * w);
    R[4] = 1.f - 2.f * (x * x + z * z);
    R[5] = 2.f * (y * z - x * w);
    R[6] = 2.f * (x * z - y * w);
    R[7] = 2.f * (y * z + x * w);
    R[8] = 1.f - 2.f * (x * x + y * y);
}

// ---------------- Kernel A: prep + asymmetric diag path ----------------
__global__ __launch_bounds__(TPB_A) void adl_prep_kernel(
    const float* __restrict__ poses_pred,
    const float* __restrict__ poses_target,
    const float* __restrict__ poses_weight,
    const float* __restrict__ points,
    const float* __restrict__ symmetry,
    float inv_scale)
{
    __shared__ float s_red[TPB_A / 32];
    const int b   = blockIdx.x;
    const int tid = threadIdx.x;

    // class selection: first i with weight[b, 4i] > 0
    int  cls   = 0;
    bool valid = false;
    #pragma unroll
    for (int i = 0; i < NC; i++) {
        float w = poses_weight[b * 4 * NC + 4 * i];
        if (!valid && w > 0.f) { cls = i; valid = true; }
    }
    if (!valid) {
        if (tid == 0) { g_is_sym[b] = 0; g_partial[b] = 0.f; }
        return;
    }

    const float* qp = poses_pred   + b * 4 * NC + 4 * cls;
    const float* qg = poses_target + b * 4 * NC + 4 * cls;
    float Rp[9], Rg[9];
    quat2rot(qp[0], qp[1], qp[2], qp[3], Rp);
    quat2rot(qg[0], qg[1], qg[2], qg[3], Rg);
    const bool   sym = symmetry[cls] > 0.f;
    const float* pts = points + (size_t)cls * NP * 3;

    float acc = 0.f;
    #pragma unroll
    for (int j = tid; j < NP / 2; j += TPB_A) {
        const float* p0 = pts + (size_t)(2 * j) * 3;
        float x0 = p0[0], y0 = p0[1], z0 = p0[2];
        float x1 = p0[3], y1 = p0[4], z1 = p0[5];

        float gx0 = Rg[0] * x0 + Rg[1] * y0 + Rg[2] * z0;
        float gy0 = Rg[3] * x0 + Rg[4] * y0 + Rg[5] * z0;
        float gz0 = Rg[6] * x0 + Rg[7] * y0 + Rg[8] * z0;
        float gx1 = Rg[0] * x1 + Rg[1] * y1 + Rg[2] * z1;
        float gy1 = Rg[3] * x1 + Rg[4] * y1 + Rg[5] * z1;
        float gz1 = Rg[6] * x1 + Rg[7] * y1 + Rg[8] * z1;

        float ax0 = Rp[0] * x0 + Rp[1] * y0 + Rp[2] * z0;
        float ay0 = Rp[3] * x0 + Rp[4] * y0 + Rp[5] * z0;
        float az0 = Rp[6] * x0 + Rp[7] * y0 + Rp[8] * z0;
        float ax1 = Rp[0] * x1 + Rp[1] * y1 + Rp[2] * z1;
        float ay1 = Rp[3] * x1 + Rp[4] * y1 + Rp[5] * z1;
        float az1 = Rp[6] * x1 + Rp[7] * y1 + Rp[8] * z1;

        if (sym) {
            float n0 = gx0 * gx0 + gy0 * gy0 + gz0 * gz0;
            float n1 = gx1 * gx1 + gy1 * gy1 + gz1 * gz1;
            ulonglong2 A, B;
            A.x = pack2(-2.f * gx0, -2.f * gx1);
            A.y = pack2(-2.f * gy0, -2.f * gy1);
            B.x = pack2(-2.f * gz0, -2.f * gz1);
            B.y = pack2(n0, n1);
            g_A[b][j]  = A;
            g_Bt[b][j] = B;
            g_xp[b][2 * j + 0] = make_float4(ax0, ay0, az0, ax0 * ax0 + ay0 * ay0 + az0 * az0);
            g_xp[b][2 * j + 1] = make_float4(ax1, ay1, az1, ax1 * ax1 + ay1 * ay1 + az1 * az1);
        } else {
            float dx0 = ax0 - gx0, dy0 = ay0 - gy0, dz0 = az0 - gz0;
            float dx1 = ax1 - gx1, dy1 = ay1 - gy1, dz1 = az1 - gz1;
            float d0 = dx0 * dx0 + dy0 * dy0 + dz0 * dz0;
            float d1 = dx1 * dx1 + dy1 * dy1 + dz1 * dz1;
            acc += 0.5f * fmaxf(d0 - MARGIN, 0.f) + 0.5f * fmaxf(d1 - MARGIN, 0.f);
        }
    }

    if (sym) {
        if (tid == 0) { g_is_sym[b] = 1; g_partial[b] = 0.f; }
        return;
    }

    // block reduce asym contribution -> own slot (no atomics)
    acc *= inv_scale;
    #pragma unroll
    for (int off = 16; off > 0; off >>= 1)
        acc += __shfl_down_sync(0xFFFFFFFFu, acc, off);
    if ((tid & 31) == 0) s_red[tid >> 5] = acc;
    __syncthreads();
    if (tid == 0) {
        float v = 0.f;
        #pragma unroll
        for (int k = 0; k < TPB_A / 32; k++) v += s_red[k];
        g_is_sym[b] = 0;
        g_partial[b] = v;
    }
}

// ---------------- Kernel B: symmetric ADD-S + final reduce ----------------
__global__ __launch_bounds__(TPB_B) void adl_sym_kernel(
    float* __restrict__ out, int out_size, float inv_scale, int B)
{
    __shared__ ulonglong2 s_A[NP / 2];
    __shared__ ulonglong2 s_B[NP / 2];
    __shared__ float s_red[TPB_B / 32];

    const int i     = blockIdx.x;
    const int b     = i / CHUNKS;
    const int chunk = i % CHUNKS;
    const int tid   = threadIdx.x;
    const int total = B * CHUNKS;

    if (g_is_sym[b]) {
        // stage packed target tile into shared (coalesced LDG.128 from L2)
        #pragma unroll
        for (int k = tid; k < NP / 2; k += TPB_B) {
            s_A[k] = g_A[b][k];
            s_B[k] = g_Bt[b][k];
        }
        __syncthreads();

        const int p0 = chunk * (2 * TPB_B) + tid;
        const int p1 = p0 + TPB_B;
        float4 x0 = g_xp[b][p0];
        float4 x1 = g_xp[b][p1];

        const ull ax0 = pack2(x0.x, x0.x), ay0 = pack2(x0.y, x0.y), az0 = pack2(x0.z, x0.z);
        const ull ax1 = pack2(x1.x, x1.x), ay1 = pack2(x1.y, x1.y), az1 = pack2(x1.z, x1.z);

        float m00 = 3.4e38f, m01 = 3.4e38f, m02 = 3.4e38f, m03 = 3.4e38f;
        float m10 = 3.4e38f, m11 = 3.4e38f, m12 = 3.4e38f, m13 = 3.4e38f;

        #pragma unroll 2
        for (int j = 0; j < NP / 2; j += 2) {
            ulonglong2 A0 = s_A[j + 0], B0 = s_B[j + 0];
            ulonglong2 A1 = s_A[j + 1], B1 = s_B[j + 1];

            ull c0 = fma2(az0, B0.x, B0.y);
            ull c1 = fma2(az0, B1.x, B1.y);
            ull c2 = fma2(az1, B0.x, B0.y);
            ull c3 = fma2(az1, B1.x, B1.y);
            ull t00 = fma2(ax0, A0.x, fma2(ay0, A0.y, c0));
            ull t01 = fma2(ax0, A1.x, fma2(ay0, A1.y, c1));
            ull t10 = fma2(ax1, A0.x, fma2(ay1, A0.y, c2));
            ull t11 = fma2(ax1, A1.x, fma2(ay1, A1.y, c3));

            float l, h;
            unpack2(t00, l, h);  m00 = fminf(m00, l);  m01 = fminf(m01, h);
            unpack2(t01, l, h);  m02 = fminf(m02, l);  m03 = fminf(m03, h);
            unpack2(t10, l, h);  m10 = fminf(m10, l);  m11 = fminf(m11, h);
            unpack2(t11, l, h);  m12 = fminf(m12, l);  m13 = fminf(m13, h);
        }

        float mn0 = fminf(fminf(m00, m01), fminf(m02, m03));
        float mn1 = fminf(fminf(m10, m11), fminf(m12, m13));
        // max(.,0) commutes with min; add constant |xp|^2 after the min
        float d0 = fmaxf(mn0 + x0.w, 0.f);
        float d1 = fmaxf(mn1 + x1.w, 0.f);

        float acc = (0.5f * fmaxf(d0 - MARGIN, 0.f) + 0.5f * fmaxf(d1 - MARGIN, 0.f)) * inv_scale;

        #pragma unroll
        for (int off = 16; off > 0; off >>= 1)
            acc += __shfl_down_sync(0xFFFFFFFFu, acc, off);
        if ((tid & 31) == 0) s_red[tid >> 5] = acc;
        __syncthreads();
        if (tid == 0) g_chunk[i] = s_red[0] + s_red[1];
    } else {
        if (tid == 0) g_chunk[i] = 0.f;
    }

    // ---- last-block final reduction (self-resetting counter) ----
    __shared__ unsigned s_last;
    __threadfence();
    if (tid == 0)
        s_last = (atomicInc(&g_done, (unsigned)total - 1) == (unsigned)total - 1);
    __syncthreads();
    if (s_last) {
        float v = 0.f;
        for (int k = tid; k < total; k += TPB_B) v += g_chunk[k];
        for (int k = tid; k < B; k += TPB_B) v += g_partial[k];
        #pragma unroll
        for (int off = 16; off > 0; off >>= 1)
            v += __shfl_down_sync(0xFFFFFFFFu, v, off);
        if ((tid & 31) == 0) s_red[tid >> 5] = v;
        __syncthreads();
        if (tid == 0) {
            out[0] = s_red[0] + s_red[1];
            for (int k = 1; k < out_size; k++) out[k] = 0.f;
        }
    }
}

extern "C" void kernel_launch(void* const* d_in, const int* in_sizes, int n_in,
                              void* d_out, int out_size) {
    const float* poses_pred   = (const float*)d_in[0];
    const float* poses_target = (const float*)d_in[1];
    const float* poses_weight = (const float*)d_in[2];
    const float* points       = (const float*)d_in[3];
    const float* symmetry     = (const float*)d_in[4];
    float* out = (float*)d_out;

    const int B = in_sizes[0] / (4 * NC);
    const float inv_scale = 1.0f / ((float)B * (float)NP);

    adl_prep_kernel<<<B, TPB_A>>>(
        poses_pred, poses_target, poses_weight, points, symmetry, inv_scale);

    adl_sym_kernel<<<B * CHUNKS, TPB_B>>>(out, out_size, inv_scale, B);
}

// round 8
// speedup vs baseline: 1.0849x; 1.0849x over previous
#include <cuda_runtime.h>

#define NC 22
#define NP 1024
#define BMAX 256
#define CHUNKS 8          // kernel B: blocks per symmetric batch
#define TPB_B 64          // kernel B threads (each handles 2 p's): CHUNKS*TPB_B*2 == NP
#define TPB_A 128
#define MARGIN 0.01f

typedef unsigned long long ull;

__device__ ulonglong2 g_A[BMAX][NP / 2];   // ((-2gx_e,-2gx_o),(-2gy_e,-2gy_o))
__device__ ulonglong2 g_Bt[BMAX][NP / 2];  // ((-2gz_e,-2gz_o),(|g_e|^2,|g_o|^2))
__device__ float4     g_xp[BMAX][NP];      // (ax, ay, az, |a|^2)
__device__ int        g_sym_cnt;                 // reset to 0 by last block each launch
__device__ int        g_sym_list[BMAX];
__device__ float      g_partial[BMAX];           // asym/diag per-batch partials
__device__ float      g_chunk[BMAX * CHUNKS];    // sym per-block partials
__device__ unsigned   g_done;                    // self-resetting via atomicInc wrap

__device__ __forceinline__ ull fma2(ull a, ull b, ull c) {
    ull d;
    asm("fma.rn.f32x2 %0, %1, %2, %3;" : "=l"(d) : "l"(a), "l"(b), "l"(c));
    return d;
}
__device__ __forceinline__ ull pack2(float lo, float hi) {
    ull d;
    asm("mov.b64 %0, {%1, %2};" : "=l"(d) : "f"(lo), "f"(hi));
    return d;
}
__device__ __forceinline__ void unpack2(ull v, float& lo, float& hi) {
    asm("mov.b64 {%0, %1}, %2;" : "=f"(lo), "=f"(hi) : "l"(v));
}

__device__ __forceinline__ void quat2rot(float w, float x, float y, float z, float* R) {
    R[0] = 1.f - 2.f * (y * y + z * z);
    R[1] = 2.f * (x * y - z * w);
    R[2] = 2.f * (x * z + y * w);
    R[3] = 2.f * (x * y + z * w);
    R[4] = 1.f - 2.f * (x * x + z * z);
    R[5] = 2.f * (y * z - x * w);
    R[6] = 2.f * (x * z - y * w);
    R[7] = 2.f * (y * z + x * w);
    R[8] = 1.f - 2.f * (x * x + y * y);
}

// ---------------- Kernel A: prep + asymmetric diag path ----------------
__global__ __launch_bounds__(TPB_A) void adl_prep_kernel(
    const float* __restrict__ poses_pred,
    const float* __restrict__ poses_target,
    const float* __restrict__ poses_weight,
    const float* __restrict__ points,
    const float* __restrict__ symmetry,
    float inv_scale)
{
    __shared__ float s_red[TPB_A / 32];
    const int b   = blockIdx.x;
    const int tid = threadIdx.x;

    // class selection: first i with weight[b, 4i] > 0
    int  cls   = 0;
    bool valid = false;
    #pragma unroll
    for (int i = 0; i < NC; i++) {
        float w = poses_weight[b * 4 * NC + 4 * i];
        if (!valid && w > 0.f) { cls = i; valid = true; }
    }
    if (!valid) {
        if (tid == 0) g_partial[b] = 0.f;
        return;
    }

    const float* qp = poses_pred   + b * 4 * NC + 4 * cls;
    const float* qg = poses_target + b * 4 * NC + 4 * cls;
    float Rp[9], Rg[9];
    quat2rot(qp[0], qp[1], qp[2], qp[3], Rp);
    quat2rot(qg[0], qg[1], qg[2], qg[3], Rg);
    const bool   sym = symmetry[cls] > 0.f;
    const float* pts = points + (size_t)cls * NP * 3;

    float acc = 0.f;
    #pragma unroll
    for (int j = tid; j < NP / 2; j += TPB_A) {
        const float* p0 = pts + (size_t)(2 * j) * 3;
        float x0 = p0[0], y0 = p0[1], z0 = p0[2];
        float x1 = p0[3], y1 = p0[4], z1 = p0[5];

        float gx0 = Rg[0] * x0 + Rg[1] * y0 + Rg[2] * z0;
        float gy0 = Rg[3] * x0 + Rg[4] * y0 + Rg[5] * z0;
        float gz0 = Rg[6] * x0 + Rg[7] * y0 + Rg[8] * z0;
        float gx1 = Rg[0] * x1 + Rg[1] * y1 + Rg[2] * z1;
        float gy1 = Rg[3] * x1 + Rg[4] * y1 + Rg[5] * z1;
        float gz1 = Rg[6] * x1 + Rg[7] * y1 + Rg[8] * z1;

        float ax0 = Rp[0] * x0 + Rp[1] * y0 + Rp[2] * z0;
        float ay0 = Rp[3] * x0 + Rp[4] * y0 + Rp[5] * z0;
        float az0 = Rp[6] * x0 + Rp[7] * y0 + Rp[8] * z0;
        float ax1 = Rp[0] * x1 + Rp[1] * y1 + Rp[2] * z1;
        float ay1 = Rp[3] * x1 + Rp[4] * y1 + Rp[5] * z1;
        float az1 = Rp[6] * x1 + Rp[7] * y1 + Rp[8] * z1;

        if (sym) {
            float n0 = gx0 * gx0 + gy0 * gy0 + gz0 * gz0;
            float n1 = gx1 * gx1 + gy1 * gy1 + gz1 * gz1;
            ulonglong2 A, B;
            A.x = pack2(-2.f * gx0, -2.f * gx1);
            A.y = pack2(-2.f * gy0, -2.f * gy1);
            B.x = pack2(-2.f * gz0, -2.f * gz1);
            B.y = pack2(n0, n1);
            g_A[b][j]  = A;
            g_Bt[b][j] = B;
            g_xp[b][2 * j + 0] = make_float4(ax0, ay0, az0, ax0 * ax0 + ay0 * ay0 + az0 * az0);
            g_xp[b][2 * j + 1] = make_float4(ax1, ay1, az1, ax1 * ax1 + ay1 * ay1 + az1 * az1);
        } else {
            float dx0 = ax0 - gx0, dy0 = ay0 - gy0, dz0 = az0 - gz0;
            float dx1 = ax1 - gx1, dy1 = ay1 - gy1, dz1 = az1 - gz1;
            float d0 = dx0 * dx0 + dy0 * dy0 + dz0 * dz0;
            float d1 = dx1 * dx1 + dy1 * dy1 + dz1 * dz1;
            acc += 0.5f * fmaxf(d0 - MARGIN, 0.f) + 0.5f * fmaxf(d1 - MARGIN, 0.f);
        }
    }

    if (sym) {
        if (tid == 0) {
            g_partial[b] = 0.f;
            __threadfence();  // tiles visible before the batch is published
            int idx = atomicAdd(&g_sym_cnt, 1);
            g_sym_list[idx] = b;
        }
        return;
    }

    // block reduce asym contribution -> own slot (no atomics on out)
    acc *= inv_scale;
    #pragma unroll
    for (int off = 16; off > 0; off >>= 1)
        acc += __shfl_down_sync(0xFFFFFFFFu, acc, off);
    if ((tid & 31) == 0) s_red[tid >> 5] = acc;
    __syncthreads();
    if (tid == 0) {
        float v = 0.f;
        #pragma unroll
        for (int k = 0; k < TPB_A / 32; k++) v += s_red[k];
        g_partial[b] = v;
    }
}

// ---------------- Kernel B: compacted symmetric ADD-S + final reduce ----------------
__global__ __launch_bounds__(TPB_B) void adl_sym_kernel(
    float* __restrict__ out, int out_size, float inv_scale, int B)
{
    __shared__ ulonglong2 s_A[NP / 2];
    __shared__ ulonglong2 s_B[NP / 2];
    __shared__ float s_red[TPB_B / 32];

    const int i     = blockIdx.x;
    const int tid   = threadIdx.x;
    const int total = B * CHUNKS;
    const int cnt   = g_sym_cnt;

    if (i < cnt * CHUNKS) {
        const int b     = g_sym_list[i / CHUNKS];
        const int chunk = i % CHUNKS;

        // stage packed target tile into shared (coalesced LDG.128 from L2)
        #pragma unroll
        for (int k = tid; k < NP / 2; k += TPB_B) {
            s_A[k] = g_A[b][k];
            s_B[k] = g_Bt[b][k];
        }
        __syncthreads();

        const int p0 = chunk * (2 * TPB_B) + tid;
        const int p1 = p0 + TPB_B;
        float4 x0 = g_xp[b][p0];
        float4 x1 = g_xp[b][p1];

        const ull ax0 = pack2(x0.x, x0.x), ay0 = pack2(x0.y, x0.y), az0 = pack2(x0.z, x0.z);
        const ull ax1 = pack2(x1.x, x1.x), ay1 = pack2(x1.y, x1.y), az1 = pack2(x1.z, x1.z);

        float m00 = 3.4e38f, m01 = 3.4e38f, m02 = 3.4e38f, m03 = 3.4e38f;
        float m10 = 3.4e38f, m11 = 3.4e38f, m12 = 3.4e38f, m13 = 3.4e38f;

        #pragma unroll 2
        for (int j = 0; j < NP / 2; j += 2) {
            ulonglong2 A0 = s_A[j + 0], B0 = s_B[j + 0];
            ulonglong2 A1 = s_A[j + 1], B1 = s_B[j + 1];

            ull c0 = fma2(az0, B0.x, B0.y);
            ull c1 = fma2(az0, B1.x, B1.y);
            ull c2 = fma2(az1, B0.x, B0.y);
            ull c3 = fma2(az1, B1.x, B1.y);
            ull t00 = fma2(ax0, A0.x, fma2(ay0, A0.y, c0));
            ull t01 = fma2(ax0, A1.x, fma2(ay0, A1.y, c1));
            ull t10 = fma2(ax1, A0.x, fma2(ay1, A0.y, c2));
            ull t11 = fma2(ax1, A1.x, fma2(ay1, A1.y, c3));

            float l, h;
            unpack2(t00, l, h);  m00 = fminf(m00, l);  m01 = fminf(m01, h);
            unpack2(t01, l, h);  m02 = fminf(m02, l);  m03 = fminf(m03, h);
            unpack2(t10, l, h);  m10 = fminf(m10, l);  m11 = fminf(m11, h);
            unpack2(t11, l, h);  m12 = fminf(m12, l);  m13 = fminf(m13, h);
        }

        float mn0 = fminf(fminf(m00, m01), fminf(m02, m03));
        float mn1 = fminf(fminf(m10, m11), fminf(m12, m13));
        // max(.,0) commutes with min; add constant |xp|^2 after the min
        float d0 = fmaxf(mn0 + x0.w, 0.f);
        float d1 = fmaxf(mn1 + x1.w, 0.f);

        float acc = (0.5f * fmaxf(d0 - MARGIN, 0.f) + 0.5f * fmaxf(d1 - MARGIN, 0.f)) * inv_scale;

        #pragma unroll
        for (int off = 16; off > 0; off >>= 1)
            acc += __shfl_down_sync(0xFFFFFFFFu, acc, off);
        if ((tid & 31) == 0) s_red[tid >> 5] = acc;
        __syncthreads();
        if (tid == 0) g_chunk[i] = s_red[0] + s_red[1];
    } else {
        if (tid == 0) g_chunk[i] = 0.f;
    }

    // ---- last-block final reduction (self-resetting counter) ----
    __shared__ unsigned s_last;
    __threadfence();
    if (tid == 0)
        s_last = (atomicInc(&g_done, (unsigned)total - 1) == (unsigned)total - 1);
    __syncthreads();
    if (s_last) {
        float v = 0.f;
        for (int k = tid; k < total; k += TPB_B) v += g_chunk[k];
        for (int k = tid; k < B; k += TPB_B) v += g_partial[k];
        #pragma unroll
        for (int off = 16; off > 0; off >>= 1)
            v += __shfl_down_sync(0xFFFFFFFFu, v, off);
        if ((tid & 31) == 0) s_red[tid >> 5] = v;
        __syncthreads();
        if (tid == 0) {
            out[0] = s_red[0] + s_red[1];
            for (int k = 1; k < out_size; k++) out[k] = 0.f;
            g_sym_cnt = 0;   // reset for next launch / graph replay
        }
    }
}

extern "C" void kernel_launch(void* const* d_in, const int* in_sizes, int n_in,
                              void* d_out, int out_size) {
    const float* poses_pred   = (const float*)d_in[0];
    const float* poses_target = (const float*)d_in[1];
    const float* poses_weight = (const float*)d_in[2];
    const float* points       = (const float*)d_in[3];
    const float* symmetry     = (const float*)d_in[4];
    float* out = (float*)d_out;

    const int B = in_sizes[0] / (4 * NC);
    const float inv_scale = 1.0f / ((float)B * (float)NP);

    adl_prep_kernel<<<B, TPB_A>>>(
        poses_pred, poses_target, poses_weight, points, symmetry, inv_scale);

    adl_sym_kernel<<<B * CHUNKS, TPB_B>>>(out, out_size, inv_scale, B);
}